// round 1
// baseline (speedup 1.0000x reference)
#include <cuda_runtime.h>
#include <cuda_bf16.h>

// Problem constants
#define BB 4
#define NN 2048
#define EE 1024
#define HH 16
#define DD 64
// M = B*N = 8192 rows

// Scratch (allocation-free rule: __device__ globals)
__device__ float g_q[BB * HH * NN * DD];     // [B,H,N,D]
__device__ float g_k[BB * HH * NN * DD];
__device__ float g_v[BB * HH * NN * DD];
__device__ float g_att[BB * NN * EE];        // [B,N,E] attention output

__device__ __forceinline__ float fast_exp2(float x) {
    float y;
    asm("ex2.approx.ftz.f32 %0, %1;" : "=f"(y) : "f"(x));
    return y;
}

// ---------------------------------------------------------------------------
// GEMM 1: QKV projection.  C[m,f] = sum_e X[m,e] * Wqkv[f,e]
// X: [8192,1024] row-major, Wqkv: [3072,1024] row-major.
// Epilogue scatters into g_q/g_k/g_v laid out [B,H,N,D].
// 128x128x16 tile, 256 threads, 8x8 micro-tile.
// ---------------------------------------------------------------------------
__global__ __launch_bounds__(256) void qkv_gemm_kernel(
    const float* __restrict__ X, const float* __restrict__ W)
{
    __shared__ float As[16][128];
    __shared__ float Bs[16][128];

    const int tid = threadIdx.x;
    const int tx = tid & 15;        // 0..15 -> column group
    const int ty = tid >> 4;        // 0..15 -> row group
    const int mBase = blockIdx.y * 128;
    const int fBase = blockIdx.x * 128;

    const int lr = tid >> 2;         // 0..63
    const int lc = (tid & 3) << 2;   // 0,4,8,12

    float acc[8][8];
#pragma unroll
    for (int i = 0; i < 8; ++i)
#pragma unroll
        for (int j = 0; j < 8; ++j) acc[i][j] = 0.f;

    for (int k0 = 0; k0 < EE; k0 += 16) {
#pragma unroll
        for (int p = 0; p < 2; ++p) {
            const int r = lr + 64 * p;
            float4 a = *(const float4*)&X[(size_t)(mBase + r) * EE + k0 + lc];
            As[lc + 0][r] = a.x; As[lc + 1][r] = a.y;
            As[lc + 2][r] = a.z; As[lc + 3][r] = a.w;
            float4 b = *(const float4*)&W[(size_t)(fBase + r) * EE + k0 + lc];
            Bs[lc + 0][r] = b.x; Bs[lc + 1][r] = b.y;
            Bs[lc + 2][r] = b.z; Bs[lc + 3][r] = b.w;
        }
        __syncthreads();

#pragma unroll
        for (int k = 0; k < 16; ++k) {
            float ar[8], br[8];
            *(float4*)&ar[0] = *(const float4*)&As[k][ty * 8];
            *(float4*)&ar[4] = *(const float4*)&As[k][ty * 8 + 4];
            *(float4*)&br[0] = *(const float4*)&Bs[k][tx * 8];
            *(float4*)&br[4] = *(const float4*)&Bs[k][tx * 8 + 4];
#pragma unroll
            for (int i = 0; i < 8; ++i)
#pragma unroll
                for (int j = 0; j < 8; ++j)
                    acc[i][j] = fmaf(ar[i], br[j], acc[i][j]);
        }
        __syncthreads();
    }

    // Epilogue: scatter into q/k/v [B,H,N,D].  A thread's 8 columns lie within
    // one head & one qkv slice (8 | 64 | 1024).
    const int f0 = fBase + tx * 8;
    const int which = f0 >> 10;          // 0=q,1=k,2=v
    const int h = (f0 >> 6) & (HH - 1);
    const int d0 = f0 & (DD - 1);
    float* base = (which == 0) ? g_q : (which == 1) ? g_k : g_v;

#pragma unroll
    for (int i = 0; i < 8; ++i) {
        const int m = mBase + ty * 8 + i;
        const int b = m >> 11;           // /2048
        const int n = m & (NN - 1);
        float* dst = base + ((size_t)((b * HH + h) * NN + n)) * DD + d0;
        *(float4*)&dst[0] = *(float4*)&acc[i][0];
        *(float4*)&dst[4] = *(float4*)&acc[i][4];
    }
}

// ---------------------------------------------------------------------------
// Flash attention. grid = (B*H, N/128), block = 128 threads.
// Thread t owns query row (qt*128 + t). Q(prescaled) and O in registers.
// K/V streamed through smem in 64-row chunks; all smem reads are uniform
// across the warp -> broadcast, conflict-free.
// ---------------------------------------------------------------------------
__global__ __launch_bounds__(128) void attn_kernel()
{
    __shared__ float Ks[64][64];
    __shared__ float Vs[64][64];

    const int bh = blockIdx.x;           // b*H + h
    const int qt = blockIdx.y;           // query tile
    const int t = threadIdx.x;

    const float scale = 0.125f;          // D^-0.5, D=64

    const float* Qp = g_q + ((size_t)bh * NN + qt * 128 + t) * DD;
    float q[DD];
#pragma unroll
    for (int i = 0; i < 16; ++i) {
        float4 v = *(const float4*)&Qp[i * 4];
        q[4 * i + 0] = v.x * scale;
        q[4 * i + 1] = v.y * scale;
        q[4 * i + 2] = v.z * scale;
        q[4 * i + 3] = v.w * scale;
    }

    float o[DD];
#pragma unroll
    for (int i = 0; i < DD; ++i) o[i] = 0.f;
    float mx = -3.0e38f;
    float l = 0.f;

    const float* Kbase = g_k + (size_t)bh * NN * DD;
    const float* Vbase = g_v + (size_t)bh * NN * DD;

    const int lrr = t >> 4;              // 0..7
    const int lcc = (t & 15) << 2;       // 0..60

    for (int kt = 0; kt < NN; kt += 64) {
        if (kt) __syncthreads();
#pragma unroll
        for (int p = 0; p < 8; ++p) {
            const int r = lrr + 8 * p;
            *(float4*)&Ks[r][lcc] = *(const float4*)&Kbase[(size_t)(kt + r) * DD + lcc];
            *(float4*)&Vs[r][lcc] = *(const float4*)&Vbase[(size_t)(kt + r) * DD + lcc];
        }
        __syncthreads();

#pragma unroll 1
        for (int sub = 0; sub < 8; ++sub) {
            const int j0 = sub * 8;
            float s[8];
#pragma unroll
            for (int jj = 0; jj < 8; ++jj) {
                const int row = j0 + jj;
                float a0 = 0.f, a1 = 0.f;
#pragma unroll
                for (int d4 = 0; d4 < 16; d4 += 2) {
                    float4 k0v = *(const float4*)&Ks[row][d4 * 4];
                    float4 k1v = *(const float4*)&Ks[row][d4 * 4 + 4];
                    a0 = fmaf(q[4 * d4 + 0], k0v.x, a0);
                    a0 = fmaf(q[4 * d4 + 1], k0v.y, a0);
                    a0 = fmaf(q[4 * d4 + 2], k0v.z, a0);
                    a0 = fmaf(q[4 * d4 + 3], k0v.w, a0);
                    a1 = fmaf(q[4 * d4 + 4], k1v.x, a1);
                    a1 = fmaf(q[4 * d4 + 5], k1v.y, a1);
                    a1 = fmaf(q[4 * d4 + 6], k1v.z, a1);
                    a1 = fmaf(q[4 * d4 + 7], k1v.w, a1);
                }
                s[jj] = a0 + a1;
            }

            // online softmax update over these 8 keys
            float mnew = mx;
#pragma unroll
            for (int jj = 0; jj < 8; ++jj) mnew = fmaxf(mnew, s[jj]);
            const float alpha = fast_exp2((mx - mnew) * 1.44269504f);
            mx = mnew;
            float psum = 0.f;
#pragma unroll
            for (int jj = 0; jj < 8; ++jj) {
                s[jj] = fast_exp2((s[jj] - mnew) * 1.44269504f);
                psum += s[jj];
            }
            l = l * alpha + psum;
#pragma unroll
            for (int d = 0; d < DD; ++d) o[d] *= alpha;

#pragma unroll
            for (int jj = 0; jj < 8; ++jj) {
                const float p = s[jj];
                const int row = j0 + jj;
#pragma unroll
                for (int d4 = 0; d4 < 16; ++d4) {
                    float4 vv = *(const float4*)&Vs[row][d4 * 4];
                    o[4 * d4 + 0] = fmaf(p, vv.x, o[4 * d4 + 0]);
                    o[4 * d4 + 1] = fmaf(p, vv.y, o[4 * d4 + 1]);
                    o[4 * d4 + 2] = fmaf(p, vv.z, o[4 * d4 + 2]);
                    o[4 * d4 + 3] = fmaf(p, vv.w, o[4 * d4 + 3]);
                }
            }
        }
    }

    const float inv = 1.f / l;
    const int b = bh >> 4;
    const int h = bh & (HH - 1);
    const int n = qt * 128 + t;
    float* dst = g_att + ((size_t)(b * NN + n)) * EE + h * DD;
#pragma unroll
    for (int d4 = 0; d4 < 16; ++d4) {
        float4 w;
        w.x = o[4 * d4 + 0] * inv;
        w.y = o[4 * d4 + 1] * inv;
        w.z = o[4 * d4 + 2] * inv;
        w.w = o[4 * d4 + 3] * inv;
        *(float4*)&dst[d4 * 4] = w;
    }
}

// ---------------------------------------------------------------------------
// GEMM 2: output projection. out[m,f] = sum_e g_att[m,e] * Wout[f,e]
// ---------------------------------------------------------------------------
__global__ __launch_bounds__(256) void out_gemm_kernel(
    const float* __restrict__ W, float* __restrict__ Cout)
{
    __shared__ float As[16][128];
    __shared__ float Bs[16][128];

    const int tid = threadIdx.x;
    const int tx = tid & 15;
    const int ty = tid >> 4;
    const int mBase = blockIdx.y * 128;
    const int fBase = blockIdx.x * 128;

    const int lr = tid >> 2;
    const int lc = (tid & 3) << 2;

    float acc[8][8];
#pragma unroll
    for (int i = 0; i < 8; ++i)
#pragma unroll
        for (int j = 0; j < 8; ++j) acc[i][j] = 0.f;

    for (int k0 = 0; k0 < EE; k0 += 16) {
#pragma unroll
        for (int p = 0; p < 2; ++p) {
            const int r = lr + 64 * p;
            float4 a = *(const float4*)&g_att[(size_t)(mBase + r) * EE + k0 + lc];
            As[lc + 0][r] = a.x; As[lc + 1][r] = a.y;
            As[lc + 2][r] = a.z; As[lc + 3][r] = a.w;
            float4 b = *(const float4*)&W[(size_t)(fBase + r) * EE + k0 + lc];
            Bs[lc + 0][r] = b.x; Bs[lc + 1][r] = b.y;
            Bs[lc + 2][r] = b.z; Bs[lc + 3][r] = b.w;
        }
        __syncthreads();

#pragma unroll
        for (int k = 0; k < 16; ++k) {
            float ar[8], br[8];
            *(float4*)&ar[0] = *(const float4*)&As[k][ty * 8];
            *(float4*)&ar[4] = *(const float4*)&As[k][ty * 8 + 4];
            *(float4*)&br[0] = *(const float4*)&Bs[k][tx * 8];
            *(float4*)&br[4] = *(const float4*)&Bs[k][tx * 8 + 4];
#pragma unroll
            for (int i = 0; i < 8; ++i)
#pragma unroll
                for (int j = 0; j < 8; ++j)
                    acc[i][j] = fmaf(ar[i], br[j], acc[i][j]);
        }
        __syncthreads();
    }

#pragma unroll
    for (int i = 0; i < 8; ++i) {
        const int m = mBase + ty * 8 + i;
        float* dst = Cout + (size_t)m * EE + fBase + tx * 8;
        *(float4*)&dst[0] = *(float4*)&acc[i][0];
        *(float4*)&dst[4] = *(float4*)&acc[i][4];
    }
}

// ---------------------------------------------------------------------------
extern "C" void kernel_launch(void* const* d_in, const int* in_sizes, int n_in,
                              void* d_out, int out_size)
{
    const float* x     = (const float*)d_in[0];   // [4,2048,1024]
    const float* w_qkv = (const float*)d_in[1];   // [3072,1024]
    const float* w_out = (const float*)d_in[2];   // [1024,1024]
    float* out = (float*)d_out;                   // [4,2048,1024]

    // 1) QKV projection -> g_q/g_k/g_v [B,H,N,D]
    {
        dim3 grid(3 * EE / 128, (BB * NN) / 128);   // (24, 64)
        qkv_gemm_kernel<<<grid, 256>>>(x, w_qkv);
    }
    // 2) Attention -> g_att [B,N,E]
    {
        dim3 grid(BB * HH, NN / 128);               // (64, 16)
        attn_kernel<<<grid, 128>>>();
    }
    // 3) Output projection -> d_out
    {
        dim3 grid(EE / 128, (BB * NN) / 128);       // (8, 64)
        out_gemm_kernel<<<grid, 256>>>(w_out, out);
    }
}